// round 10
// baseline (speedup 1.0000x reference)
#include <cuda_runtime.h>
#include <cuda_bf16.h>
#include <cstdint>

// ---------------------------------------------------------------------------
// GAT layer, tf32 tensor cores, persistent CTAs + cp.async double buffering.
//   K1: h = x @ W.T. 148 persistent CTAs (1/SM), 512 thr (16 warps, 4Mx4N),
//       BM=128 tiles. W staged+tf32-converted once per CTA; A tiles
//       prefetched with cp.async (raw fp32), fragments cvt'd in registers.
//   K2: per edge, read h[src],h[dst] from d_out (pre-scatter), attention,
//       stage 0.1*attn*h_src into scratch.
//   K3: atomicAdd staged contributions into d_out[dst].
// edge_index is int32 (jax x64 disabled).
// ---------------------------------------------------------------------------

#define IN_F  128
#define OUT_F 128
#define HEADS 4
#define HDIM  32

#define BM    128
#define LDSTR 132     // row stride (floats) = 528B; LDSM rows -> distinct 16B banks
#define NCTA  148
#define NTHR  512

#define MAX_E 2048
__device__ float g_contrib[MAX_E * OUT_F];

__device__ __forceinline__ uint32_t f2tf32(float f) {
    uint32_t u;
    asm("cvt.rna.tf32.f32 %0, %1;" : "=r"(u) : "f"(f));
    return u;
}

__device__ __forceinline__ uint32_t smem_u32(const void* p) {
    uint32_t a;
    asm("{ .reg .u64 t; cvta.to.shared.u64 t, %1; cvt.u32.u64 %0, t; }"
        : "=r"(a) : "l"(p));
    return a;
}

__device__ __forceinline__ void ldsm_x4(uint32_t& r0, uint32_t& r1,
                                        uint32_t& r2, uint32_t& r3,
                                        uint32_t addr) {
    asm volatile("ldmatrix.sync.aligned.m8n8.x4.shared.b16 {%0,%1,%2,%3}, [%4];"
                 : "=r"(r0), "=r"(r1), "=r"(r2), "=r"(r3) : "r"(addr));
}

__device__ __forceinline__ void mma_tf32(float* c, const uint32_t* a, const uint32_t* b) {
    asm volatile(
        "mma.sync.aligned.m16n8k8.row.col.f32.tf32.tf32.f32 "
        "{%0,%1,%2,%3}, {%4,%5,%6,%7}, {%8,%9}, {%0,%1,%2,%3};"
        : "+f"(c[0]), "+f"(c[1]), "+f"(c[2]), "+f"(c[3])
        : "r"(a[0]), "r"(a[1]), "r"(a[2]), "r"(a[3]), "r"(b[0]), "r"(b[1]));
}

__device__ __forceinline__ void cpasync16(uint32_t dst, const void* src) {
    asm volatile("cp.async.cg.shared.global [%0], [%1], 16;" :: "r"(dst), "l"(src));
}

// Prefetch one 128x128 fp32 A tile (raw bits) into buf. 8 x 16B per thread.
__device__ __forceinline__ void prefetch_tile(
    const float* __restrict__ X, int rowBase, int M, uint32_t bufAddr, int tid)
{
    #pragma unroll
    for (int i = 0; i < 8; i++) {
        int fid = tid + i * NTHR;
        int row = fid >> 5, c4 = fid & 31;
        int gr = rowBase + row; if (gr >= M) gr = M - 1;
        cpasync16(bufAddr + (uint32_t)(row * LDSTR + c4 * 4) * 4,
                  X + (size_t)gr * IN_F + c4 * 4);
    }
}

// ---- K1: persistent tf32 GEMM ----------------------------------------------
__global__ __launch_bounds__(NTHR, 1) void gat_gemm_tf32(
    const float* __restrict__ X,   // [M,128]
    const float* __restrict__ W,   // [128,128] row-major (out = X * W^T)
    float* __restrict__ O,         // [M,128]
    int M)
{
    extern __shared__ uint32_t smem[];
    uint32_t* A0 = smem;                         // [128][LDSTR] buffer 0
    uint32_t* A1 = smem + BM * LDSTR;            // buffer 1
    uint32_t* Ws = smem + 2 * BM * LDSTR;        // [128][LDSTR] tf32 W

    const int tid = threadIdx.x;
    const int nTiles = (M + BM - 1) / BM;
    const uint32_t aBuf[2] = { smem_u32(A0), smem_u32(A1) };

    // Prologue: prefetch first tile into buf0, then stage+convert W.
    int t0 = blockIdx.x;
    if (t0 < nTiles) {
        prefetch_tile(X, t0 * BM, M, aBuf[0], tid);
        asm volatile("cp.async.commit_group;" ::: "memory");
    }
    #pragma unroll
    for (int i = 0; i < 8; i++) {
        int fid = tid + i * NTHR;
        int n = fid >> 5, c4 = fid & 31;
        float4 v = *reinterpret_cast<const float4*>(W + (size_t)n * IN_F + c4 * 4);
        uint4 t = make_uint4(f2tf32(v.x), f2tf32(v.y), f2tf32(v.z), f2tf32(v.w));
        *reinterpret_cast<uint4*>(Ws + n * LDSTR + c4 * 4) = t;
    }

    const int warp = tid >> 5, lane = tid & 31;
    const int mw = warp >> 2, nw = warp & 3;     // 4 M-warps x 4 N-warps
    const int g = lane >> 2, tig = lane & 3;

    // LDSM lane addresses. Warp tile: rows [mw*32, mw*32+32), cols [nw*32, +32).
    const int aRow = (lane & 7) + ((lane >> 3) & 1) * 8;
    const int aCol = ((lane >> 4) & 1) * 4;
    uint32_t aOff[2];   // byte offset within a buffer, per m-tile (16 rows)
    #pragma unroll
    for (int mt = 0; mt < 2; mt++)
        aOff[mt] = (uint32_t)((mw * 32 + mt * 16 + aRow) * LDSTR + aCol) * 4;

    const int bRow = (lane & 7) + ((lane >> 4) & 1) * 8;
    const int bCol = ((lane >> 3) & 1) * 4;
    uint32_t bAddr[2];  // n-tile pairs: {2j, 2j+1} at rows nw*32 + j*16
    #pragma unroll
    for (int j = 0; j < 2; j++)
        bAddr[j] = smem_u32(Ws + (nw * 32 + j * 16 + bRow) * LDSTR + bCol);

    int it = 0;
    for (int t = t0; t < nTiles; t += NCTA, it++) {
        const uint32_t cur = aBuf[it & 1];
        const uint32_t nxt = aBuf[(it + 1) & 1];

        asm volatile("cp.async.wait_group 0;" ::: "memory");
        __syncthreads();                       // tile data + W visible; prev
                                               // compute on 'nxt' buffer done
        int tn = t + NCTA;
        if (tn < nTiles) {
            prefetch_tile(X, tn * BM, M, nxt, tid);
            asm volatile("cp.async.commit_group;" ::: "memory");
        }

        float acc[2][4][4];
        #pragma unroll
        for (int mt = 0; mt < 2; mt++)
            #pragma unroll
            for (int nt = 0; nt < 4; nt++)
                #pragma unroll
                for (int r = 0; r < 4; r++) acc[mt][nt][r] = 0.0f;

        #pragma unroll
        for (int ks = 0; ks < 16; ks++) {
            const uint32_t koff = ks * 32;
            uint32_t a[2][4];
            #pragma unroll
            for (int mt = 0; mt < 2; mt++)
                ldsm_x4(a[mt][0], a[mt][1], a[mt][2], a[mt][3],
                        cur + aOff[mt] + koff);
            uint32_t b[4][2];
            #pragma unroll
            for (int j = 0; j < 2; j++)
                ldsm_x4(b[2*j][0], b[2*j][1], b[2*j+1][0], b[2*j+1][1],
                        bAddr[j] + koff);
            // A arrived as raw fp32: convert fragments to tf32 (rna).
            #pragma unroll
            for (int mt = 0; mt < 2; mt++)
                #pragma unroll
                for (int r = 0; r < 4; r++)
                    a[mt][r] = f2tf32(__uint_as_float(a[mt][r]));
            #pragma unroll
            for (int mt = 0; mt < 2; mt++)
                #pragma unroll
                for (int nt = 0; nt < 4; nt++)
                    mma_tf32(acc[mt][nt], a[mt], b[nt]);
        }

        // Epilogue: c0/c1 -> (row g, cols 2tig,2tig+1); c2/c3 -> row g+8.
        const int rowBase = t * BM + mw * 32;
        #pragma unroll
        for (int mt = 0; mt < 2; mt++) {
            int r0 = rowBase + mt * 16 + g;
            int r1 = r0 + 8;
            #pragma unroll
            for (int nt = 0; nt < 4; nt++) {
                int c = nw * 32 + nt * 8 + tig * 2;
                if (r0 < M)
                    *reinterpret_cast<float2*>(O + (size_t)r0 * OUT_F + c) =
                        make_float2(acc[mt][nt][0], acc[mt][nt][1]);
                if (r1 < M)
                    *reinterpret_cast<float2*>(O + (size_t)r1 * OUT_F + c) =
                        make_float2(acc[mt][nt][2], acc[mt][nt][3]);
            }
        }
        __syncthreads();   // all LDSM on 'cur' done before it is refilled
    }
}

// ---- K2: gather h from O, compute attn, stage contribution -----------------
__global__ __launch_bounds__(128) void gat_edge_gather(
    const float* __restrict__ O,
    const int* __restrict__ EI,        // [2,E]: row0 src, row1 dst
    const float* __restrict__ A,       // [HEADS, 2*HDIM]
    int E)
{
    const int e = blockIdx.x;
    const int tid = threadIdx.x;
    const int src = EI[e];
    const int dst = EI[E + e];

    float hs = O[(size_t)src * OUT_F + tid];
    float hd = O[(size_t)dst * OUT_F + tid];

    const int h = tid >> 5;
    const int d = tid & 31;
    float ev = hs * A[h * (2 * HDIM) + d] + hd * A[h * (2 * HDIM) + HDIM + d];
    #pragma unroll
    for (int off = 16; off > 0; off >>= 1)
        ev += __shfl_xor_sync(0xffffffffu, ev, off);
    float attn = ev > 0.0f ? ev : 0.2f * ev;

    g_contrib[e * OUT_F + tid] = 0.1f * attn * hs;
}

// ---- K3: scatter staged contributions --------------------------------------
__global__ __launch_bounds__(128) void gat_edge_scatter(
    float* __restrict__ O,
    const int* __restrict__ EI,
    int E)
{
    const int e = blockIdx.x;
    const int tid = threadIdx.x;
    const int dst = EI[E + e];
    atomicAdd(&O[(size_t)dst * OUT_F + tid], g_contrib[e * OUT_F + tid]);
}

extern "C" void kernel_launch(void* const* d_in, const int* in_sizes, int n_in,
                              void* d_out, int out_size)
{
    const float* x  = (const float*)d_in[0];
    const int*   ei = (const int*)d_in[1];
    const float* W  = (const float*)d_in[2];
    const float* a  = (const float*)d_in[3];
    float* out = (float*)d_out;

    const int M = in_sizes[0] / IN_F;   // 200000
    int E = in_sizes[1] / 2;            // 500
    if (E > MAX_E) E = MAX_E;

    const int smemBytes = 3 * BM * LDSTR * sizeof(uint32_t);  // ~198KB
    cudaFuncSetAttribute(gat_gemm_tf32,
                         cudaFuncAttributeMaxDynamicSharedMemorySize, smemBytes);

    gat_gemm_tf32<<<NCTA, NTHR, smemBytes>>>(x, W, out, M);
    gat_edge_gather<<<E, 128>>>(out, ei, a, E);
    gat_edge_scatter<<<E, 128>>>(out, ei, E);
}

// round 15
// speedup vs baseline: 1.0584x; 1.0584x over previous
#include <cuda_runtime.h>
#include <cuda_bf16.h>
#include <cstdint>

// ---------------------------------------------------------------------------
// GAT layer, tf32 mma.sync, persistent CTAs + cp.async double buffering +
// explicit K-step software pipeline (fragments for ks+1 loaded before MMAs
// of ks issue, breaking the LDSM->MMA dependency chain).
//   K1: h = x @ W.T. 148 persistent CTAs (1/SM), 256 thr (8 warps, 4Mx2N),
//       BM=128 tiles. W staged+tf32-converted once; A via cp.async raw fp32,
//       fragments cvt'd in registers.
//   K2: per edge, read h[src],h[dst] from d_out, attention, stage contrib.
//   K3: atomicAdd staged contributions into d_out[dst].
// edge_index is int32 (jax x64 disabled). tcgen05 unavailable: harness PTX
// target is compute_103 (no 'a'), ptxas rejects tcgen05 -> mma.sync path.
// ---------------------------------------------------------------------------

#define IN_F  128
#define OUT_F 128
#define HEADS 4
#define HDIM  32

#define BM    128
#define LDSTR 132     // row stride (floats) = 528B; LDSM rows -> distinct 16B banks
#define NCTA  148
#define NTHR  256

#define MAX_E 2048
__device__ float g_contrib[MAX_E * OUT_F];

__device__ __forceinline__ uint32_t f2tf32(float f) {
    uint32_t u;
    asm("cvt.rna.tf32.f32 %0, %1;" : "=r"(u) : "f"(f));
    return u;
}

__device__ __forceinline__ uint32_t smem_u32(const void* p) {
    uint32_t a;
    asm("{ .reg .u64 t; cvta.to.shared.u64 t, %1; cvt.u32.u64 %0, t; }"
        : "=r"(a) : "l"(p));
    return a;
}

__device__ __forceinline__ void ldsm_x4(uint32_t& r0, uint32_t& r1,
                                        uint32_t& r2, uint32_t& r3,
                                        uint32_t addr) {
    asm volatile("ldmatrix.sync.aligned.m8n8.x4.shared.b16 {%0,%1,%2,%3}, [%4];"
                 : "=r"(r0), "=r"(r1), "=r"(r2), "=r"(r3) : "r"(addr));
}

__device__ __forceinline__ void mma_tf32(float* c, const uint32_t* a, const uint32_t* b) {
    asm volatile(
        "mma.sync.aligned.m16n8k8.row.col.f32.tf32.tf32.f32 "
        "{%0,%1,%2,%3}, {%4,%5,%6,%7}, {%8,%9}, {%0,%1,%2,%3};"
        : "+f"(c[0]), "+f"(c[1]), "+f"(c[2]), "+f"(c[3])
        : "r"(a[0]), "r"(a[1]), "r"(a[2]), "r"(a[3]), "r"(b[0]), "r"(b[1]));
}

__device__ __forceinline__ void cpasync16(uint32_t dst, const void* src) {
    asm volatile("cp.async.cg.shared.global [%0], [%1], 16;" :: "r"(dst), "l"(src));
}

// Prefetch one 128x128 fp32 A tile (raw bits) into buf. 16 x 16B per thread.
__device__ __forceinline__ void prefetch_tile(
    const float* __restrict__ X, int rowBase, int M, uint32_t bufAddr, int tid)
{
    #pragma unroll
    for (int i = 0; i < 16; i++) {
        int fid = tid + i * NTHR;
        int row = fid >> 5, c4 = fid & 31;
        int gr = rowBase + row; if (gr >= M) gr = M - 1;
        cpasync16(bufAddr + (uint32_t)(row * LDSTR + c4 * 4) * 4,
                  X + (size_t)gr * IN_F + c4 * 4);
    }
}

// ---- K1: persistent tf32 GEMM with K-step pipeline -------------------------
__global__ __launch_bounds__(NTHR, 1) void gat_gemm_tf32(
    const float* __restrict__ X,   // [M,128]
    const float* __restrict__ W,   // [128,128] row-major (out = X * W^T)
    float* __restrict__ O,         // [M,128]
    int M)
{
    extern __shared__ uint32_t smem[];
    uint32_t* A0 = smem;                         // [128][LDSTR] buffer 0
    uint32_t* A1 = smem + BM * LDSTR;            // buffer 1
    uint32_t* Ws = smem + 2 * BM * LDSTR;        // [128][LDSTR] tf32 W

    const int tid = threadIdx.x;
    const int nTiles = (M + BM - 1) / BM;
    const uint32_t aBuf[2] = { smem_u32(A0), smem_u32(A1) };

    // Prologue: prefetch first tile into buf0, then stage+convert W.
    int t0 = blockIdx.x;
    if (t0 < nTiles) {
        prefetch_tile(X, t0 * BM, M, aBuf[0], tid);
        asm volatile("cp.async.commit_group;" ::: "memory");
    }
    #pragma unroll
    for (int i = 0; i < 16; i++) {
        int fid = tid + i * NTHR;
        int n = fid >> 5, c4 = fid & 31;
        float4 v = *reinterpret_cast<const float4*>(W + (size_t)n * IN_F + c4 * 4);
        uint4 t = make_uint4(f2tf32(v.x), f2tf32(v.y), f2tf32(v.z), f2tf32(v.w));
        *reinterpret_cast<uint4*>(Ws + n * LDSTR + c4 * 4) = t;
    }

    const int warp = tid >> 5, lane = tid & 31;
    const int mw = warp >> 1, nw = warp & 1;     // 4 M-warps x 2 N-warps
    const int g = lane >> 2, tig = lane & 3;

    // LDSM lane addresses (A addr recomputed per buffer via offset).
    const int aRow = (lane & 7) + ((lane >> 3) & 1) * 8;
    const int aCol = ((lane >> 4) & 1) * 4;
    uint32_t aOff[2];   // byte offset within a buffer, per m-tile
    #pragma unroll
    for (int mt = 0; mt < 2; mt++)
        aOff[mt] = (uint32_t)((mw * 32 + mt * 16 + aRow) * LDSTR + aCol) * 4;

    const int bRow = (lane & 7) + ((lane >> 4) & 1) * 8;
    const int bCol = ((lane >> 3) & 1) * 4;
    uint32_t bAddr[4];
    #pragma unroll
    for (int j = 0; j < 4; j++)
        bAddr[j] = smem_u32(Ws + (nw * 64 + j * 16 + bRow) * LDSTR + bCol);

    int it = 0;
    for (int t = t0; t < nTiles; t += NCTA, it++) {
        const uint32_t cur = aBuf[it & 1];
        const uint32_t nxt = aBuf[(it + 1) & 1];

        asm volatile("cp.async.wait_group 0;" ::: "memory");
        __syncthreads();    // tile data visible; all warps done with 'nxt'
                            // (this sync also orders prev-iter compute
                            //  before the refill below)
        int tn = t + NCTA;
        if (tn < nTiles) {
            prefetch_tile(X, tn * BM, M, nxt, tid);
            asm volatile("cp.async.commit_group;" ::: "memory");
        }

        float acc[2][8][4];
        #pragma unroll
        for (int mt = 0; mt < 2; mt++)
            #pragma unroll
            for (int nt = 0; nt < 8; nt++)
                #pragma unroll
                for (int r = 0; r < 4; r++) acc[mt][nt][r] = 0.0f;

        // K-step software pipeline: 2-stage fragment buffers.
        uint32_t afr[2][2][4];   // [stage][mt][reg]  (raw fp32 bits)
        uint32_t bfr[2][8][2];   // [stage][nt][reg]  (tf32, pre-converted W)

        // preload ks=0 into stage 0
        #pragma unroll
        for (int mt = 0; mt < 2; mt++)
            ldsm_x4(afr[0][mt][0], afr[0][mt][1], afr[0][mt][2], afr[0][mt][3],
                    cur + aOff[mt]);
        #pragma unroll
        for (int j = 0; j < 4; j++)
            ldsm_x4(bfr[0][2*j][0], bfr[0][2*j][1], bfr[0][2*j+1][0], bfr[0][2*j+1][1],
                    bAddr[j]);

        #pragma unroll
        for (int ks = 0; ks < 16; ks++) {
            const int st  = ks & 1;
            const int nst = st ^ 1;
            if (ks < 15) {
                const uint32_t koff = (uint32_t)(ks + 1) * 32;
                #pragma unroll
                for (int mt = 0; mt < 2; mt++)
                    ldsm_x4(afr[nst][mt][0], afr[nst][mt][1],
                            afr[nst][mt][2], afr[nst][mt][3],
                            cur + aOff[mt] + koff);
                #pragma unroll
                for (int j = 0; j < 4; j++)
                    ldsm_x4(bfr[nst][2*j][0], bfr[nst][2*j][1],
                            bfr[nst][2*j+1][0], bfr[nst][2*j+1][1],
                            bAddr[j] + koff);
            }
            uint32_t a[2][4];
            #pragma unroll
            for (int mt = 0; mt < 2; mt++)
                #pragma unroll
                for (int r = 0; r < 4; r++)
                    a[mt][r] = f2tf32(__uint_as_float(afr[st][mt][r]));
            #pragma unroll
            for (int mt = 0; mt < 2; mt++)
                #pragma unroll
                for (int nt = 0; nt < 8; nt++)
                    mma_tf32(acc[mt][nt], a[mt], bfr[st][nt]);
        }

        // Epilogue: c0/c1 -> (row g, cols 2tig,2tig+1); c2/c3 -> row g+8.
        const int rowBase = t * BM + mw * 32;
        #pragma unroll
        for (int mt = 0; mt < 2; mt++) {
            int r0 = rowBase + mt * 16 + g;
            int r1 = r0 + 8;
            #pragma unroll
            for (int nt = 0; nt < 8; nt++) {
                int c = nw * 64 + nt * 8 + tig * 2;
                if (r0 < M)
                    *reinterpret_cast<float2*>(O + (size_t)r0 * OUT_F + c) =
                        make_float2(acc[mt][nt][0], acc[mt][nt][1]);
                if (r1 < M)
                    *reinterpret_cast<float2*>(O + (size_t)r1 * OUT_F + c) =
                        make_float2(acc[mt][nt][2], acc[mt][nt][3]);
            }
        }
        // no end-of-loop __syncthreads: the wait_group+sync at the top of the
        // next iteration orders all warps' compute before the buffer refill.
    }
}

// ---- K2: gather h from O, compute attn, stage contribution -----------------
__global__ __launch_bounds__(128) void gat_edge_gather(
    const float* __restrict__ O,
    const int* __restrict__ EI,        // [2,E]: row0 src, row1 dst
    const float* __restrict__ A,       // [HEADS, 2*HDIM]
    int E)
{
    const int e = blockIdx.x;
    const int tid = threadIdx.x;
    const int src = EI[e];
    const int dst = EI[E + e];

    float hs = O[(size_t)src * OUT_F + tid];
    float hd = O[(size_t)dst * OUT_F + tid];

    const int h = tid >> 5;
    const int d = tid & 31;
    float ev = hs * A[h * (2 * HDIM) + d] + hd * A[h * (2 * HDIM) + HDIM + d];
    #pragma unroll
    for (int off = 16; off > 0; off >>= 1)
        ev += __shfl_xor_sync(0xffffffffu, ev, off);
    float attn = ev > 0.0f ? ev : 0.2f * ev;

    g_contrib[e * OUT_F + tid] = 0.1f * attn * hs;
}

// ---- K3: scatter staged contributions --------------------------------------
__global__ __launch_bounds__(128) void gat_edge_scatter(
    float* __restrict__ O,
    const int* __restrict__ EI,
    int E)
{
    const int e = blockIdx.x;
    const int tid = threadIdx.x;
    const int dst = EI[E + e];
    atomicAdd(&O[(size_t)dst * OUT_F + tid], g_contrib[e * OUT_F + tid]);
}

extern "C" void kernel_launch(void* const* d_in, const int* in_sizes, int n_in,
                              void* d_out, int out_size)
{
    const float* x  = (const float*)d_in[0];
    const int*   ei = (const int*)d_in[1];
    const float* W  = (const float*)d_in[2];
    const float* a  = (const float*)d_in[3];
    float* out = (float*)d_out;

    const int M = in_sizes[0] / IN_F;   // 200000
    int E = in_sizes[1] / 2;            // 500
    if (E > MAX_E) E = MAX_E;

    const int smemBytes = 3 * BM * LDSTR * sizeof(uint32_t);  // ~198KB
    cudaFuncSetAttribute(gat_gemm_tf32,
                         cudaFuncAttributeMaxDynamicSharedMemorySize, smemBytes);

    gat_gemm_tf32<<<NCTA, NTHR, smemBytes>>>(x, W, out, M);
    gat_edge_gather<<<E, 128>>>(out, ei, a, E);
    gat_edge_scatter<<<E, 128>>>(out, ei, E);
}